// round 6
// baseline (speedup 1.0000x reference)
#include <cuda_runtime.h>
#include <cstdint>

// Problem constants (fixed by setup_inputs)
#define BB      48
#define NKC     800
#define NMBON   20
#define NFBN    60
#define NDAN    20
#define NREC    100
#define TT      121
#define NSTEP   120
#define W_MAXC  0.05f

#define NTHREADS 512
#define NCTA     (BB * 2)

// scratch: r_kc transposed to [B, T, NKC]
__device__ float g_rkcT[(long)BB * TT * NKC];

// ---------------------------------------------------------------------------
// Transpose r_kc [B, NKC, T] -> g_rkcT [B, T, NKC]
// ---------------------------------------------------------------------------
__global__ void transpose_kernel(const float* __restrict__ rkc) {
    __shared__ float tile[32][33];
    const int bz = blockIdx.z;
    const int kt = blockIdx.y;
    const int tt = blockIdx.x;
    const int tx = threadIdx.x, ty = threadIdx.y;

    int k = kt * 32 + ty;
    int t = tt * 32 + tx;
    if (t < TT)
        tile[ty][tx] = rkc[((long)bz * NKC + k) * TT + t];
    __syncthreads();
    int t2 = tt * 32 + ty;
    int k2 = kt * 32 + tx;
    if (t2 < TT)
        g_rkcT[((long)bz * TT + t2) * NKC + k2] = tile[tx][ty];
}

// ---------------------------------------------------------------------------
// Main RNN kernel: cluster of 2 CTAs per batch (m-split), 512 threads/CTA.
//   g = tid>>8, q = tid&255. Owners (q<200) hold rows m_off+g*5+0..4, chunk q.
//   Phase C: 400 threads, i=tid>>2, h=tid&3, Wr coefficients in REGISTERS.
//   Senders tid 400..409 (owners idle in C). Staging tid 456..511.
// ---------------------------------------------------------------------------
// shared layout (floats):
//  mbar 4 | imb 40 | rkc3 2400 | rbkc 1600 | r 200 | bias 100 | ifbn 128 |
//  red 8*10=80 | rdan 20 | rbdan 20 | wro 20 | wext 120
#define SM_FLOATS (4 + 40 + 2400 + 1600 + 200 + 100 + 128 + 80 + 20 + 20 + 20 + 120)

__global__ __launch_bounds__(NTHREADS, 1) __cluster_dims__(2, 1, 1)
void rnn_kernel(
    const float* __restrict__ r_ext,     // [B, 2, T]
    const float* __restrict__ time_arr,  // [T]
    const float* __restrict__ W_kc0,     // [B, 20, 800]
    const float* __restrict__ wt0,       // [B, 20, 800]
    const float* __restrict__ W_recur,   // [100, 100]
    const float* __restrict__ W_readout, // [1, 20]
    const float* __restrict__ bias,      // [100]
    const float* __restrict__ W_ext,     // [60, 2]
    float* __restrict__ out)
{
    extern __shared__ float sm[];
    float* mbar_f  = sm;                  // 4  (2 x u64 mbarriers)
    float* imb     = sm + 4;              // 2 x 20
    float* rkc3    = imb + 40;            // 3 x 800 ring (16B aligned)
    float* rbkc    = rkc3 + 2400;         // 2 x 800
    float* r_s     = rbkc + 1600;         // 2 x 100
    float* bias_s  = r_s + 200;           // 100
    float* ifbn    = bias_s + 100;        // 2 x 64
    float* red_s   = ifbn + 128;          // 8 slots x 10 local rows
    float* rdan_s  = red_s + 80;          // 20
    float* rbdan_s = rdan_s + 20;         // 20
    float* wro_s   = rbdan_s + 20;        // 20
    float* wext_s  = wro_s + 20;          // 120

    const int tid  = threadIdx.x;
    const int bx   = blockIdx.x;
    const int b    = bx >> 1;
    const int rank = bx & 1;
    const int prank = rank ^ 1;
    const int m_off = rank * 10;
    const int lane = tid & 31;
    const int warp = tid >> 5;
    const int g    = tid >> 8;            // 0/1
    const int q    = tid & 255;           // k-chunk
    const bool owner = (q < 200);

    const bool is_c    = (tid < 400);
    const int  ci = tid >> 2;             // output index i (0..99)
    const int  ch = tid & 3;              // j-parity class
    const unsigned cmask = (warp < 12) ? 0xffffffffu : 0x0000ffffu;

    const bool is_send  = (tid >= 400 && tid < 410);
    const int  send_mm  = tid - 400;      // local row 0..9
    const bool is_stage = (tid >= 456);
    const int  sstg = tid - 456;          // 0..55

    float* out_r  = out;
    float* out_W  = out + (long)TT * BB * NREC;
    float* out_wt = out_W + (long)TT * BB * NMBON * NKC;
    float* out_ro = out_wt + (long)TT * BB * NMBON * NKC;

    const float dt  = time_arr[1] - time_arr[0];
    const float a_r = dt;                 // dt / TAU_R
    const float a_w = dt * 0.2f;          // dt / TAU_W

    const float* rkc_g = g_rkcT + (long)b * TT * NKC;

    const uint32_t imb_loc  = (uint32_t)__cvta_generic_to_shared(imb);
    const uint32_t mbar_loc = (uint32_t)__cvta_generic_to_shared(mbar_f);
    uint32_t imb_rem, mbar_rem;
    asm("mapa.shared::cluster.u32 %0, %1, %2;" : "=r"(imb_rem)  : "r"(imb_loc),  "r"(prank));
    asm("mapa.shared::cluster.u32 %0, %1, %2;" : "=r"(mbar_rem) : "r"(mbar_loc), "r"(prank));

    // ---------------- init ----------------
    if (tid == 0) {
        asm volatile("mbarrier.init.shared.b64 [%0], 10;" :: "r"(mbar_loc)     : "memory");
        asm volatile("mbarrier.init.shared.b64 [%0], 10;" :: "r"(mbar_loc + 8) : "memory");
    }
    if (tid < NREC)     bias_s[tid] = bias[tid];
    if (tid < NMBON)    wro_s[tid]  = W_readout[tid];
    if (tid >= 32 && tid < 32 + NFBN * 2) wext_s[tid - 32] = W_ext[tid - 32];
    if (tid < NREC) {
        float r0 = (tid < NMBON) ? 0.f : 0.1f;
        r_s[tid] = r0;
        if (rank == 0) out_r[(long)b * NREC + tid] = r0;
    }
    if (tid < NDAN) rbdan_s[tid] = 0.1f;
    for (int k = tid; k < NKC; k += NTHREADS) {
        float v = rkc_g[k];
        rkc3[k] = v;
        rbkc[800 + k] = v;
    }
    __syncthreads();   // wext_s ready
    if (tid < NFBN) {
        float e0 = r_ext[((long)b * 2 + 0) * TT];
        float e1 = r_ext[((long)b * 2 + 1) * TT];
        ifbn[tid] = wext_s[tid * 2] * e0 + wext_s[tid * 2 + 1] * e1;
    }
    if (tid == 0 && rank == 0) out_ro[b] = 0.f;

    // recurrent weights in registers (C threads): wreg[bq] = Wr[ci][ch+4bq]
    float wreg[25];
    if (is_c) {
#pragma unroll
        for (int bq = 0; bq < 25; ++bq) {
            int j = ch + 4 * bq;
            float v = W_recur[ci * NREC + j];
            if (ci < NMBON && j >= NREC - NDAN) v = 0.f;
            wreg[bq] = v;
        }
    } else {
#pragma unroll
        for (int bq = 0; bq < 25; ++bq) wreg[bq] = 0.f;
    }

    float4 Wv[5], wtv[5];
    if (owner) {
        const long ibase = ((long)b * NMBON + m_off + g * 5) * NKC + q * 4;
        const long obase = ((long)b) * (NMBON * NKC) + (long)(m_off + g * 5) * NKC + q * 4;
#pragma unroll
        for (int mm = 0; mm < 5; ++mm) {
            float4 w  = *(const float4*)(W_kc0 + ibase + (long)mm * NKC);
            float4 wt = *(const float4*)(wt0   + ibase + (long)mm * NKC);
            Wv[mm] = w; wtv[mm] = wt;
            *(float4*)(out_W  + obase + (long)mm * NKC) = w;
            *(float4*)(out_wt + obase + (long)mm * NKC) = wt;
        }
    } else {
#pragma unroll
        for (int mm = 0; mm < 5; ++mm) {
            Wv[mm]  = make_float4(0.f, 0.f, 0.f, 0.f);
            wtv[mm] = make_float4(0.f, 0.f, 0.f, 0.f);
        }
    }
    __syncthreads();
    asm volatile("barrier.cluster.arrive.aligned;" ::: "memory");
    asm volatile("barrier.cluster.wait.aligned;"   ::: "memory");

    // ---------------- time loop ----------------
    int pcur = 0;
    for (int t = 0; t < NSTEP; ++t) {
        const int pnext = (pcur == 2) ? 0 : pcur + 1;
        const int hb  = t & 1;
        const int par = (t >> 1) & 1;

        float e0 = 0.f, e1 = 0.f;
        // ---- prefetch rkc(t+1) into ring[pnext] (staging 456..511) ----
        if (is_stage) {
            const float* gsrc = rkc_g + (long)(t + 1) * NKC;
#pragma unroll
            for (int j = 0; j < 4; ++j) {
                int c = sstg + 56 * j;
                if (c < 200) {
                    uint32_t dst = (uint32_t)__cvta_generic_to_shared(rkc3 + pnext * 800 + c * 4);
                    asm volatile("cp.async.cg.shared.global [%0], [%1], 16;\n"
                                 :: "r"(dst), "l"(gsrc + c * 4));
                }
            }
            asm volatile("cp.async.commit_group;\n" ::: "memory");
            e0 = r_ext[((long)b * 2 + 0) * TT + (t + 1)];
            e1 = r_ext[((long)b * 2 + 1) * TT + (t + 1)];
        }

        // ---- Phase B: I_mbon partials — ALL 512 threads, full-mask shuffles ----
        {
            float4 kc = make_float4(0.f, 0.f, 0.f, 0.f);
            if (owner) kc = *(const float4*)(rkc3 + pcur * 800 + q * 4);
#pragma unroll
            for (int mm = 0; mm < 5; ++mm) {
                float4 w = Wv[mm];   // zero for non-owners
                float p = w.x * kc.x + w.y * kc.y + w.z * kc.z + w.w * kc.w;
                p += __shfl_xor_sync(0xffffffffu, p, 16);
                p += __shfl_xor_sync(0xffffffffu, p, 8);
                p += __shfl_xor_sync(0xffffffffu, p, 4);
                p += __shfl_xor_sync(0xffffffffu, p, 2);
                p += __shfl_xor_sync(0xffffffffu, p, 1);
                if (lane == 0)
                    red_s[(warp & 7) * 10 + g * 5 + mm] = p;   // slot = warp&7
            }
        }
        __syncthreads();   // bar1: red_s ready

        // ---- Phase C (tid<400) ∥ senders (400..409) ∥ staging (456..511) ----
        const float* rc = r_s + hb * NREC;
        float* rn_buf   = r_s + (hb ^ 1) * NREC;
        if (is_c) {
            float a0 = 0.f, a1 = 0.f;
#pragma unroll
            for (int bq = 0; bq < 25; ++bq) {
                float rv = rc[ch + 4 * bq];
                if (bq & 1) a1 = fmaf(rv, wreg[bq], a1);
                else        a0 = fmaf(rv, wreg[bq], a0);
            }
            float p = a0 + a1;
            p += __shfl_xor_sync(cmask, p, 1);
            p += __shfl_xor_sync(cmask, p, 2);   // all 4 lanes of group hold dot

            if (ch == 0) {
                const int i = ci;
                float itot;
                if (i < NMBON) {
                    const int li = i - m_off;
                    if (li >= 0 && li < 10) {
                        float s0 = 0.f, s1 = 0.f, s2 = 0.f, s3 = 0.f;
                        s0 = red_s[0 * 10 + li] + red_s[4 * 10 + li];
                        s1 = red_s[1 * 10 + li] + red_s[5 * 10 + li];
                        s2 = red_s[2 * 10 + li] + red_s[6 * 10 + li];
                        s3 = red_s[3 * 10 + li] + red_s[7 * 10 + li];
                        itot = (s0 + s1) + (s2 + s3);
                    } else {
                        uint32_t done;
                        asm volatile(
                            "{\n\t.reg .pred p;\n\t"
                            "mbarrier.try_wait.parity.acquire.cluster.shared::cta.b64 p, [%1], %2;\n\t"
                            "selp.b32 %0, 1, 0, p;\n\t}"
                            : "=r"(done) : "r"(mbar_loc + hb * 8), "r"(par) : "memory");
                        while (!done) {
                            asm volatile(
                                "{\n\t.reg .pred p;\n\t"
                                "mbarrier.try_wait.parity.acquire.cluster.shared::cta.b64 p, [%1], %2, 0x989680;\n\t"
                                "selp.b32 %0, 1, 0, p;\n\t}"
                                : "=r"(done) : "r"(mbar_loc + hb * 8), "r"(par) : "memory");
                        }
                        itot = imb[hb * 20 + i];
                    }
                } else if (i < NMBON + NFBN) {
                    itot = ifbn[hb * 64 + (i - NMBON)];
                } else {
                    itot = 0.f;
                }
                float pre  = p + bias_s[i] + itot;
                float relu = fmaxf(pre, 0.f);
                float rold = rc[i];
                float rn   = fmaf(a_r, relu - rold, rold);
                rn_buf[i] = rn;
                if (rank == 0) out_r[((long)(t + 1) * BB + b) * NREC + i] = rn;
                if (i >= NREC - NDAN) {
                    int m = i - (NREC - NDAN);
                    rdan_s[m] = rn;
                    float rb = rbdan_s[m];
                    rbdan_s[m] = fmaf(a_w, rn - rb, rb);
                }
            }
        } else if (is_send) {
            // sum 8 slots for local row send_mm, ship to peer
            float s0 = red_s[0 * 10 + send_mm] + red_s[4 * 10 + send_mm];
            float s1 = red_s[1 * 10 + send_mm] + red_s[5 * 10 + send_mm];
            float s2 = red_s[2 * 10 + send_mm] + red_s[6 * 10 + send_mm];
            float s3 = red_s[3 * 10 + send_mm] + red_s[7 * 10 + send_mm];
            float v = (s0 + s1) + (s2 + s3);
            asm volatile("st.shared::cluster.f32 [%0], %1;"
                         :: "r"(imb_rem + (hb * 20 + m_off + send_mm) * 4), "f"(v) : "memory");
            asm volatile("mbarrier.arrive.release.cluster.shared::cluster.b64 _, [%0];"
                         :: "r"(mbar_rem + hb * 8) : "memory");
        } else if (is_stage) {
            // rb_kc(t) update + ifbn(t+1) + cp.async wait
#pragma unroll
            for (int j = 0; j < 4; ++j) {
                int c = sstg + 56 * j;
                if (c < 200) {
                    float4 kc = *(const float4*)(rkc3 + pcur * 800 + c * 4);
                    float4 bk = *(const float4*)(rbkc + (hb ^ 1) * 800 + c * 4);
                    bk.x = fmaf(a_w, kc.x - bk.x, bk.x);
                    bk.y = fmaf(a_w, kc.y - bk.y, bk.y);
                    bk.z = fmaf(a_w, kc.z - bk.z, bk.z);
                    bk.w = fmaf(a_w, kc.w - bk.w, bk.w);
                    *(float4*)(rbkc + hb * 800 + c * 4) = bk;
                }
            }
            if (sstg < NFBN)
                ifbn[(hb ^ 1) * 64 + sstg] = wext_s[sstg * 2] * e0 + wext_s[sstg * 2 + 1] * e1;
            if (sstg >= 52) {   // 4 threads cover f = 56..59
                int f = sstg + 4;
                ifbn[(hb ^ 1) * 64 + f] = wext_s[f * 2] * e0 + wext_s[f * 2 + 1] * e1;
            }
            asm volatile("cp.async.wait_group 0;\n" ::: "memory");
        }
        __syncthreads();   // bar2: r_new, rdan/rbdan, rbkc(t), rkc(t+1) ready

        // ---- Phase D: plasticity update + streaming stores ----
        if (owner) {
            float4 kc = *(const float4*)(rkc3 + pcur * 800 + q * 4);
            float4 bk = *(const float4*)(rbkc + hb * 800 + q * 4);
            const long obase = ((long)(t + 1) * BB + b) * (NMBON * NKC)
                             + (long)(m_off + g * 5) * NKC + q * 4;
#pragma unroll
            for (int mm = 0; mm < 5; ++mm) {
                const int m = m_off + g * 5 + mm;
                const float rbd = rbdan_s[m];
                const float rd  = rdan_s[m];
                float4 w = Wv[mm], wt = wtv[mm];
                float dw;
                dw = fmaf(rbd, kc.x, -(rd * bk.x)); wt.x = fmaf(dw, dt, wt.x);
                dw = fmaf(rbd, kc.y, -(rd * bk.y)); wt.y = fmaf(dw, dt, wt.y);
                dw = fmaf(rbd, kc.z, -(rd * bk.z)); wt.z = fmaf(dw, dt, wt.z);
                dw = fmaf(rbd, kc.w, -(rd * bk.w)); wt.w = fmaf(dw, dt, wt.w);
                w.x = fminf(fmaxf(fmaf(a_w, wt.x - w.x, w.x), 0.f), W_MAXC);
                w.y = fminf(fmaxf(fmaf(a_w, wt.y - w.y, w.y), 0.f), W_MAXC);
                w.z = fminf(fmaxf(fmaf(a_w, wt.z - w.z, w.z), 0.f), W_MAXC);
                w.w = fminf(fmaxf(fmaf(a_w, wt.w - w.w, w.w), 0.f), W_MAXC);
                Wv[mm] = w; wtv[mm] = wt;
                *(float4*)(out_W  + obase + (long)mm * NKC) = w;
                *(float4*)(out_wt + obase + (long)mm * NKC) = wt;
            }
        }
        if (warp == 0 && rank == 0) {   // readout from r_new
            float v = (lane < NMBON) ? rn_buf[lane] * wro_s[lane] : 0.f;
            v += __shfl_xor_sync(0xffffffffu, v, 16);
            v += __shfl_xor_sync(0xffffffffu, v, 8);
            v += __shfl_xor_sync(0xffffffffu, v, 4);
            v += __shfl_xor_sync(0xffffffffu, v, 2);
            v += __shfl_xor_sync(0xffffffffu, v, 1);
            if (lane == 0) out_ro[(long)(t + 1) * BB + b] = v;
        }
        pcur = pnext;
    }

    asm volatile("barrier.cluster.arrive.aligned;" ::: "memory");
    asm volatile("barrier.cluster.wait.aligned;"   ::: "memory");
}

// ---------------------------------------------------------------------------
extern "C" void kernel_launch(void* const* d_in, const int* in_sizes, int n_in,
                              void* d_out, int out_size) {
    const float* r_kc      = (const float*)d_in[0];
    const float* r_ext     = (const float*)d_in[1];
    const float* time_arr  = (const float*)d_in[2];
    const float* W_kc0     = (const float*)d_in[3];
    const float* wt0       = (const float*)d_in[4];
    const float* W_recur   = (const float*)d_in[5];
    const float* W_readout = (const float*)d_in[6];
    const float* bias      = (const float*)d_in[7];
    const float* W_ext     = (const float*)d_in[8];
    float* out = (float*)d_out;

    cudaFuncSetAttribute(rnn_kernel, cudaFuncAttributeMaxDynamicSharedMemorySize,
                         SM_FLOATS * (int)sizeof(float));

    transpose_kernel<<<dim3(4, 25, BB), dim3(32, 32)>>>(r_kc);
    rnn_kernel<<<NCTA, NTHREADS, SM_FLOATS * (int)sizeof(float)>>>(
        r_ext, time_arr, W_kc0, wt0, W_recur, W_readout, bias, W_ext, out);
}

// round 7
// speedup vs baseline: 1.0966x; 1.0966x over previous
#include <cuda_runtime.h>
#include <cstdint>

// Problem constants (fixed by setup_inputs)
#define BB      48
#define NKC     800
#define NMBON   20
#define NFBN    60
#define NDAN    20
#define NREC    100
#define TT      121
#define NSTEP   120
#define W_MAXC  0.05f

#define NTHREADS 512
#define NCTA     (BB * 2)

// scratch: r_kc transposed to [B, T, NKC]
__device__ float g_rkcT[(long)BB * TT * NKC];

// ---------------------------------------------------------------------------
// Transpose r_kc [B, NKC, T] -> g_rkcT [B, T, NKC]
// ---------------------------------------------------------------------------
__global__ void transpose_kernel(const float* __restrict__ rkc) {
    __shared__ float tile[32][33];
    const int bz = blockIdx.z;
    const int kt = blockIdx.y;
    const int tt = blockIdx.x;
    const int tx = threadIdx.x, ty = threadIdx.y;

    int k = kt * 32 + ty;
    int t = tt * 32 + tx;
    if (t < TT)
        tile[ty][tx] = rkc[((long)bz * NKC + k) * TT + t];
    __syncthreads();
    int t2 = tt * 32 + ty;
    int k2 = kt * 32 + tx;
    if (t2 < TT)
        g_rkcT[((long)bz * TT + t2) * NKC + k2] = tile[tx][ty];
}

// ---------------------------------------------------------------------------
// Cluster of 2 CTAs per batch (m-split), 512 threads/CTA.
// Owners: tid 0..199 (g=0) & 256..455 (g=1): 5 rows (m_off+g*5+mm) x chunk q.
// Warp 7 (224..255): skips Phase B; lanes 0..19 do DAN-C pre-bar1; post-bar1
//   lanes 0..9 send+local-mbon, 10..19 peer-mbon (wait), 20..31 fbn 20..31.
// Warp 15 (480..511): skips B; staging (cp.async ring, rb_kc, ifbn) pre-bar1;
//   lanes 0..23 fbn dots 32..55 post-bar1; all wait cp group.
// Warp 6 lanes 8..19 (200..211): fbn 56..67. Warp 14 lanes 8..19: fbn 68..79.
// Phase D (owners) runs right after bar1, overlapped with dots + exchange.
// ---------------------------------------------------------------------------
// shared layout (floats):
//  mbar 4 | imb 40 | WrM 100*100 | rkc3 2400 | rbkc 1600 | r 200 | bias 100 |
//  ifbn 128 | red 8*10 | rdan 20 | rbdan 20 | wro 20 | wext 120
#define SM_FLOATS (4 + 40 + 10000 + 2400 + 1600 + 200 + 100 + 128 + 80 + 20 + 20 + 20 + 120)

__global__ __launch_bounds__(NTHREADS, 1) __cluster_dims__(2, 1, 1)
void rnn_kernel(
    const float* __restrict__ r_ext,     // [B, 2, T]
    const float* __restrict__ time_arr,  // [T]
    const float* __restrict__ W_kc0,     // [B, 20, 800]
    const float* __restrict__ wt0,       // [B, 20, 800]
    const float* __restrict__ W_recur,   // [100, 100]
    const float* __restrict__ W_readout, // [1, 20]
    const float* __restrict__ bias,      // [100]
    const float* __restrict__ W_ext,     // [60, 2]
    float* __restrict__ out)
{
    extern __shared__ float sm[];
    float* mbar_f  = sm;                  // 4  (2 x u64 mbarriers)
    float* imb     = sm + 4;              // 2 x 20
    float* WrM     = imb + 40;            // 100 x 100 row-major (rows<20: cols 80..99 zeroed)
    float* rkc3    = WrM + 10000;         // 3 x 800 ring
    float* rbkc    = rkc3 + 2400;         // 2 x 800
    float* r_s     = rbkc + 1600;         // 2 x 100
    float* bias_s  = r_s + 200;           // 100
    float* ifbn    = bias_s + 100;        // 2 x 64
    float* red_s   = ifbn + 128;          // 8 slots x 10 local rows (slot 7 stays 0)
    float* rdan_s  = red_s + 80;          // 20
    float* rbdan_s = rdan_s + 20;         // 20
    float* wro_s   = rbdan_s + 20;        // 20
    float* wext_s  = wro_s + 20;          // 120

    const int tid  = threadIdx.x;
    const int bx   = blockIdx.x;
    const int b    = bx >> 1;
    const int rank = bx & 1;
    const int prank = rank ^ 1;
    const int m_off = rank * 10;
    const int lane = tid & 31;
    const int warp = tid >> 5;
    const int g    = tid >> 8;            // 0/1
    const int q    = tid & 255;           // k-chunk
    const bool owner = (q < 200);

    // post-bar1 C-dot assignment (output index, -1 = none)
    int ci2 = -1;
    bool is_loc = false, is_peer = false;
    if (warp == 7) {
        if (lane < 10)      { ci2 = m_off + lane;            is_loc  = true; }
        else if (lane < 20) { ci2 = (m_off ^ 10) + lane - 10; is_peer = true; }
        else                { ci2 = 20 + (lane - 20); }      // 20..31
    } else if (warp == 15) {
        if (lane < 24) ci2 = 32 + lane;                      // 32..55
    } else if (warp == 6) {
        if (lane >= 8 && lane < 20) ci2 = 56 + (lane - 8);   // 56..67
    } else if (warp == 14) {
        if (lane >= 8 && lane < 20) ci2 = 68 + (lane - 8);   // 68..79
    }

    float* out_r  = out;
    float* out_W  = out + (long)TT * BB * NREC;
    float* out_wt = out_W + (long)TT * BB * NMBON * NKC;
    float* out_ro = out_wt + (long)TT * BB * NMBON * NKC;

    const float dt  = time_arr[1] - time_arr[0];
    const float a_r = dt;                 // dt / TAU_R
    const float a_w = dt * 0.2f;          // dt / TAU_W

    const float* rkc_g = g_rkcT + (long)b * TT * NKC;

    const uint32_t imb_loc  = (uint32_t)__cvta_generic_to_shared(imb);
    const uint32_t mbar_loc = (uint32_t)__cvta_generic_to_shared(mbar_f);
    uint32_t imb_rem, mbar_rem;
    asm("mapa.shared::cluster.u32 %0, %1, %2;" : "=r"(imb_rem)  : "r"(imb_loc),  "r"(prank));
    asm("mapa.shared::cluster.u32 %0, %1, %2;" : "=r"(mbar_rem) : "r"(mbar_loc), "r"(prank));

    // ---------------- init ----------------
    if (tid == 0) {
        asm volatile("mbarrier.init.shared.b64 [%0], 10;" :: "r"(mbar_loc)     : "memory");
        asm volatile("mbarrier.init.shared.b64 [%0], 10;" :: "r"(mbar_loc + 8) : "memory");
    }
    // WrM row-major copy with MBON->DAN zero patch
    for (int idx = tid; idx < NREC * NREC; idx += NTHREADS) {
        int i = idx / NREC, j = idx % NREC;
        float v = W_recur[idx];
        if (i < NMBON && j >= NREC - NDAN) v = 0.f;
        WrM[idx] = v;
    }
    if (tid < 80)       red_s[tid] = 0.f;            // slot 7 must stay zero
    if (tid < NREC)     bias_s[tid] = bias[tid];
    if (tid < NMBON)    wro_s[tid]  = W_readout[tid];
    if (tid >= 128 && tid < 128 + NFBN * 2) wext_s[tid - 128] = W_ext[tid - 128];
    if (tid < NREC) {
        float r0 = (tid < NMBON) ? 0.f : 0.1f;
        r_s[tid] = r0;
        if (rank == 0) out_r[(long)b * NREC + tid] = r0;
    }
    if (tid < NDAN) rbdan_s[tid] = 0.1f;
    for (int k = tid; k < NKC; k += NTHREADS) {
        float v = rkc_g[k];
        rkc3[k] = v;
        rbkc[800 + k] = v;   // rbkc buffer 1 holds rb_kc(before step 0); step0 writes buf 0
    }
    __syncthreads();   // wext_s ready
    if (tid < NFBN) {
        float e0 = r_ext[((long)b * 2 + 0) * TT];
        float e1 = r_ext[((long)b * 2 + 1) * TT];
        ifbn[tid] = wext_s[tid * 2] * e0 + wext_s[tid * 2 + 1] * e1;
    }
    if (tid == 0 && rank == 0) out_ro[b] = 0.f;

    float4 Wv[5], wtv[5];
    if (owner) {
        const long ibase = ((long)b * NMBON + m_off + g * 5) * NKC + q * 4;
        const long obase = ((long)b) * (NMBON * NKC) + (long)(m_off + g * 5) * NKC + q * 4;
#pragma unroll
        for (int mm = 0; mm < 5; ++mm) {
            float4 w  = *(const float4*)(W_kc0 + ibase + (long)mm * NKC);
            float4 wt = *(const float4*)(wt0   + ibase + (long)mm * NKC);
            Wv[mm] = w; wtv[mm] = wt;
            *(float4*)(out_W  + obase + (long)mm * NKC) = w;
            *(float4*)(out_wt + obase + (long)mm * NKC) = wt;
        }
    } else {
#pragma unroll
        for (int mm = 0; mm < 5; ++mm) {
            Wv[mm]  = make_float4(0.f, 0.f, 0.f, 0.f);
            wtv[mm] = make_float4(0.f, 0.f, 0.f, 0.f);
        }
    }
    __syncthreads();
    asm volatile("barrier.cluster.arrive.aligned;" ::: "memory");
    asm volatile("barrier.cluster.wait.aligned;"   ::: "memory");

    // ---------------- time loop ----------------
    int pcur = 0;
    for (int t = 0; t < NSTEP; ++t) {
        const int pnext = (pcur == 2) ? 0 : pcur + 1;
        const int hb  = t & 1;
        const int par = (t >> 1) & 1;

        const float* rc = r_s + hb * NREC;
        float* rn_buf   = r_s + (hb ^ 1) * NREC;

        // ======== pre-bar1: B (warps !=7 mod 8) ∥ DAN-C (warp7) ∥ staging (warp15)
        if ((warp & 7) != 7) {
            // Phase B: I_mbon partials, full-mask shuffles (warp-uniform)
            float4 kc = make_float4(0.f, 0.f, 0.f, 0.f);
            if (owner) kc = *(const float4*)(rkc3 + pcur * 800 + q * 4);
#pragma unroll
            for (int mm = 0; mm < 5; ++mm) {
                float4 w = Wv[mm];   // zero for non-owners in mixed warps
                float p = w.x * kc.x + w.y * kc.y + w.z * kc.z + w.w * kc.w;
                p += __shfl_xor_sync(0xffffffffu, p, 16);
                p += __shfl_xor_sync(0xffffffffu, p, 8);
                p += __shfl_xor_sync(0xffffffffu, p, 4);
                p += __shfl_xor_sync(0xffffffffu, p, 2);
                p += __shfl_xor_sync(0xffffffffu, p, 1);
                if (lane == 0)
                    red_s[(warp & 7) * 10 + g * 5 + mm] = p;
            }
        } else if (warp == 7) {
            // DAN-C: r_new for i = 80..99 (I_tot = 0). Depends only on r(t).
            if (lane < NDAN) {
                const int i = 80 + lane;
                const float4* wrow = (const float4*)(WrM + i * NREC);
                const float4* r4   = (const float4*)rc;
                float a0 = 0.f, a1 = 0.f, a2 = 0.f, a3 = 0.f;
#pragma unroll
                for (int jb = 0; jb < 25; ++jb) {
                    float4 wv = wrow[jb];
                    float4 rv = r4[jb];
                    a0 = fmaf(wv.x, rv.x, a0);
                    a1 = fmaf(wv.y, rv.y, a1);
                    a2 = fmaf(wv.z, rv.z, a2);
                    a3 = fmaf(wv.w, rv.w, a3);
                }
                float pre  = (a0 + a1) + (a2 + a3) + bias_s[i];
                float relu = fmaxf(pre, 0.f);
                float rold = rc[i];
                float rn   = fmaf(a_r, relu - rold, rold);
                rn_buf[i] = rn;
                if (rank == 0) out_r[((long)(t + 1) * BB + b) * NREC + i] = rn;
                rdan_s[lane] = rn;
                float rb = rbdan_s[lane];
                rbdan_s[lane] = fmaf(a_w, rn - rb, rb);
            }
        } else {
            // warp 15: staging. cp.async rkc(t+1) -> ring[pnext]; rb_kc(t); ifbn(t+1)
            const float* gsrc = rkc_g + (long)(t + 1) * NKC;
#pragma unroll
            for (int j = 0; j < 7; ++j) {
                int c = lane + 32 * j;
                if (c < 200) {
                    uint32_t dst = (uint32_t)__cvta_generic_to_shared(rkc3 + pnext * 800 + c * 4);
                    asm volatile("cp.async.cg.shared.global [%0], [%1], 16;\n"
                                 :: "r"(dst), "l"(gsrc + c * 4));
                }
            }
            asm volatile("cp.async.commit_group;\n" ::: "memory");
            float e0 = r_ext[((long)b * 2 + 0) * TT + (t + 1)];
            float e1 = r_ext[((long)b * 2 + 1) * TT + (t + 1)];
#pragma unroll
            for (int j = 0; j < 7; ++j) {
                int c = lane + 32 * j;
                if (c < 200) {
                    float4 kc = *(const float4*)(rkc3 + pcur * 800 + c * 4);
                    float4 bk = *(const float4*)(rbkc + (hb ^ 1) * 800 + c * 4);
                    bk.x = fmaf(a_w, kc.x - bk.x, bk.x);
                    bk.y = fmaf(a_w, kc.y - bk.y, bk.y);
                    bk.z = fmaf(a_w, kc.z - bk.z, bk.z);
                    bk.w = fmaf(a_w, kc.w - bk.w, bk.w);
                    *(float4*)(rbkc + hb * 800 + c * 4) = bk;
                }
            }
            {
                int f = lane;
                ifbn[(hb ^ 1) * 64 + f] = wext_s[f * 2] * e0 + wext_s[f * 2 + 1] * e1;
                f = lane + 32;
                if (f < NFBN)
                    ifbn[(hb ^ 1) * 64 + f] = wext_s[f * 2] * e0 + wext_s[f * 2 + 1] * e1;
            }
        }
        __syncthreads();   // bar1: red_s, rdan/rbdan(new), rbkc(t), ifbn(t+1) ready

        // ======== post-bar1: send FIRST, then D (owners) ∥ C dots ∥ cp wait
        float vloc = 0.f;
        if (warp == 7 && lane < 10) {
            vloc = red_s[0 * 10 + lane] + red_s[1 * 10 + lane] + red_s[2 * 10 + lane]
                 + red_s[3 * 10 + lane] + red_s[4 * 10 + lane] + red_s[5 * 10 + lane]
                 + red_s[6 * 10 + lane];
            asm volatile("st.shared::cluster.f32 [%0], %1;"
                         :: "r"(imb_rem + (hb * 20 + m_off + lane) * 4), "f"(vloc) : "memory");
            asm volatile("mbarrier.arrive.release.cluster.shared::cluster.b64 _, [%0];"
                         :: "r"(mbar_rem + hb * 8) : "memory");
        }

        if (owner) {
            // Phase D: plasticity update + streaming stores (overlaps dots/exchange)
            float4 kc = *(const float4*)(rkc3 + pcur * 800 + q * 4);
            float4 bk = *(const float4*)(rbkc + hb * 800 + q * 4);
            const long obase = ((long)(t + 1) * BB + b) * (NMBON * NKC)
                             + (long)(m_off + g * 5) * NKC + q * 4;
#pragma unroll
            for (int mm = 0; mm < 5; ++mm) {
                const int m = m_off + g * 5 + mm;
                const float rbd = rbdan_s[m];
                const float rd  = rdan_s[m];
                float4 w = Wv[mm], wt = wtv[mm];
                float dw;
                dw = fmaf(rbd, kc.x, -(rd * bk.x)); wt.x = fmaf(dw, dt, wt.x);
                dw = fmaf(rbd, kc.y, -(rd * bk.y)); wt.y = fmaf(dw, dt, wt.y);
                dw = fmaf(rbd, kc.z, -(rd * bk.z)); wt.z = fmaf(dw, dt, wt.z);
                dw = fmaf(rbd, kc.w, -(rd * bk.w)); wt.w = fmaf(dw, dt, wt.w);
                w.x = fminf(fmaxf(fmaf(a_w, wt.x - w.x, w.x), 0.f), W_MAXC);
                w.y = fminf(fmaxf(fmaf(a_w, wt.y - w.y, w.y), 0.f), W_MAXC);
                w.z = fminf(fmaxf(fmaf(a_w, wt.z - w.z, w.z), 0.f), W_MAXC);
                w.w = fminf(fmaxf(fmaf(a_w, wt.w - w.w, w.w), 0.f), W_MAXC);
                Wv[mm] = w; wtv[mm] = wt;
                *(float4*)(out_W  + obase + (long)mm * NKC) = w;
                *(float4*)(out_wt + obase + (long)mm * NKC) = wt;
            }
        }

        if (ci2 >= 0) {
            // MBON/FBN r-update: full 100-dot from row-major WrM (conflict-free)
            const int i = ci2;
            const float4* wrow = (const float4*)(WrM + i * NREC);
            const float4* r4   = (const float4*)rc;
            float a0 = 0.f, a1 = 0.f, a2 = 0.f, a3 = 0.f;
#pragma unroll
            for (int jb = 0; jb < 25; ++jb) {
                float4 wv = wrow[jb];
                float4 rv = r4[jb];
                a0 = fmaf(wv.x, rv.x, a0);
                a1 = fmaf(wv.y, rv.y, a1);
                a2 = fmaf(wv.z, rv.z, a2);
                a3 = fmaf(wv.w, rv.w, a3);
            }
            float p = (a0 + a1) + (a2 + a3);
            float itot;
            if (is_loc) {
                itot = vloc;
            } else if (is_peer) {
                uint32_t done;
                asm volatile(
                    "{\n\t.reg .pred p;\n\t"
                    "mbarrier.try_wait.parity.acquire.cluster.shared::cta.b64 p, [%1], %2;\n\t"
                    "selp.b32 %0, 1, 0, p;\n\t}"
                    : "=r"(done) : "r"(mbar_loc + hb * 8), "r"(par) : "memory");
                while (!done) {
                    asm volatile(
                        "{\n\t.reg .pred p;\n\t"
                        "mbarrier.try_wait.parity.acquire.cluster.shared::cta.b64 p, [%1], %2, 0x989680;\n\t"
                        "selp.b32 %0, 1, 0, p;\n\t}"
                        : "=r"(done) : "r"(mbar_loc + hb * 8), "r"(par) : "memory");
                }
                itot = imb[hb * 20 + i];
            } else {
                itot = ifbn[hb * 64 + (i - NMBON)];
            }
            float pre  = p + bias_s[i] + itot;
            float relu = fmaxf(pre, 0.f);
            float rold = rc[i];
            float rn   = fmaf(a_r, relu - rold, rold);
            rn_buf[i] = rn;
            if (rank == 0) out_r[((long)(t + 1) * BB + b) * NREC + i] = rn;
        }

        if (warp == 15)
            asm volatile("cp.async.wait_group 0;\n" ::: "memory");

        __syncthreads();   // bar2: r_new complete, red_s consumed, ring[pnext] ready

        if (warp == 0 && rank == 0) {   // readout from r_new
            float v = (lane < NMBON) ? rn_buf[lane] * wro_s[lane] : 0.f;
            v += __shfl_xor_sync(0xffffffffu, v, 16);
            v += __shfl_xor_sync(0xffffffffu, v, 8);
            v += __shfl_xor_sync(0xffffffffu, v, 4);
            v += __shfl_xor_sync(0xffffffffu, v, 2);
            v += __shfl_xor_sync(0xffffffffu, v, 1);
            if (lane == 0) out_ro[(long)(t + 1) * BB + b] = v;
        }
        pcur = pnext;
    }

    asm volatile("barrier.cluster.arrive.aligned;" ::: "memory");
    asm volatile("barrier.cluster.wait.aligned;"   ::: "memory");
}

// ---------------------------------------------------------------------------
extern "C" void kernel_launch(void* const* d_in, const int* in_sizes, int n_in,
                              void* d_out, int out_size) {
    const float* r_kc      = (const float*)d_in[0];
    const float* r_ext     = (const float*)d_in[1];
    const float* time_arr  = (const float*)d_in[2];
    const float* W_kc0     = (const float*)d_in[3];
    const float* wt0       = (const float*)d_in[4];
    const float* W_recur   = (const float*)d_in[5];
    const float* W_readout = (const float*)d_in[6];
    const float* bias      = (const float*)d_in[7];
    const float* W_ext     = (const float*)d_in[8];
    float* out = (float*)d_out;

    cudaFuncSetAttribute(rnn_kernel, cudaFuncAttributeMaxDynamicSharedMemorySize,
                         SM_FLOATS * (int)sizeof(float));

    transpose_kernel<<<dim3(4, 25, BB), dim3(32, 32)>>>(r_kc);
    rnn_kernel<<<NCTA, NTHREADS, SM_FLOATS * (int)sizeof(float)>>>(
        r_ext, time_arr, W_kc0, wt0, W_recur, W_readout, bias, W_ext, out);
}